// round 11
// baseline (speedup 1.0000x reference)
#include <cuda_runtime.h>
#include <cstdint>

// Problem dims
#define BB 32     // batch
#define TE 800    // encoder timesteps
#define TD 400    // decoder timesteps
#define ED 256    // encoder feature dim
#define AD 128    // attention dim
#define GD 256    // GRU dim
#define ID 80     // input dim

// ---------------------------------------------------------------------------
// Scratch (static __device__ globals — the sanctioned scratch mechanism)
// ---------------------------------------------------------------------------
__device__ float g_ep[(size_t)BB * TE * AD];    // enc_proj  (b, t, a)
__device__ float g_encT[(size_t)BB * ED * TE];  // enc_feat transposed (b, e, t)
__device__ float g_gix[(size_t)BB * TD * 768];  // x-part of GRU gates + folded biases (b, t, r)
__device__ float g_WA[512 * 512];               // rows 0..511: [W_ih[:,80:336] | W_hh]  (r,z gates)
__device__ float g_WB[256 * 256];               // n-gate: W_ih[512+i, 80:336]
__device__ float g_WC[256 * 256];               // n-gate: W_hh[512+i, :]
__device__ float g_WO[80 * 512];                // W_out permuted to [ctx-part | h-part]

// ---------------------------------------------------------------------------
// Helpers
// ---------------------------------------------------------------------------
__device__ __forceinline__ float dot4(float4 a, float4 b) {
    return fmaf(a.x, b.x, fmaf(a.y, b.y, fmaf(a.z, b.z, a.w * b.w)));
}
__device__ __forceinline__ float wsum(float v) {
    v += __shfl_down_sync(0xffffffffu, v, 16);
    v += __shfl_down_sync(0xffffffffu, v, 8);
    v += __shfl_down_sync(0xffffffffu, v, 4);
    v += __shfl_down_sync(0xffffffffu, v, 2);
    v += __shfl_down_sync(0xffffffffu, v, 1);
    return v;  // lane 0 holds the sum
}
__device__ __forceinline__ float wmaxr(float v) {
    v = fmaxf(v, __shfl_down_sync(0xffffffffu, v, 16));
    v = fmaxf(v, __shfl_down_sync(0xffffffffu, v, 8));
    v = fmaxf(v, __shfl_down_sync(0xffffffffu, v, 4));
    v = fmaxf(v, __shfl_down_sync(0xffffffffu, v, 2));
    v = fmaxf(v, __shfl_down_sync(0xffffffffu, v, 1));
    return v;
}
__device__ __forceinline__ float wallmax(float v) {
    #pragma unroll
    for (int s = 16; s > 0; s >>= 1) v = fmaxf(v, __shfl_xor_sync(0xffffffffu, v, s));
    return v;
}
__device__ __forceinline__ float wallsum(float v) {
    #pragma unroll
    for (int s = 16; s > 0; s >>= 1) v += __shfl_xor_sync(0xffffffffu, v, s);
    return v;
}
__device__ __forceinline__ float ftanh(float x) {
    float y;
    asm("tanh.approx.f32 %0, %1;" : "=f"(y) : "f"(x));
    return y;
}

// ---------------------------------------------------------------------------
// P4: weight repack
// ---------------------------------------------------------------------------
__global__ void prep_repack(const float* __restrict__ W_ih,
                            const float* __restrict__ W_hh,
                            const float* __restrict__ W_out) {
    int stride = gridDim.x * blockDim.x;
    int g = blockIdx.x * blockDim.x + threadIdx.x;
    const int NA = 512 * 512, NB = 256 * 256, NC = 256 * 256, NO = 80 * 512;
    for (int i = g; i < NA; i += stride) {
        int r = i >> 9, c = i & 511;
        g_WA[i] = (c < 256) ? W_ih[(size_t)r * 336 + 80 + c]
                            : W_hh[(size_t)r * 256 + (c - 256)];
    }
    for (int i = g; i < NB; i += stride) {
        int r = i >> 8, c = i & 255;
        g_WB[i] = W_ih[(size_t)(512 + r) * 336 + 80 + c];
    }
    for (int i = g; i < NC; i += stride) {
        int r = i >> 8, c = i & 255;
        g_WC[i] = W_hh[(size_t)(512 + r) * 256 + c];
    }
    for (int i = g; i < NO; i += stride) {
        int r = i >> 9, c = i & 511;
        // sh_in layout is [ctx ; h]; W_out columns are [h ; ctx] -> swap halves
        g_WO[i] = (c < 256) ? W_out[(size_t)r * 512 + 256 + c]
                            : W_out[(size_t)r * 512 + (c - 256)];
    }
}

// ---------------------------------------------------------------------------
// P1: enc_proj[b][t][a] = sum_e enc[b][t][e] * W_enc[a][e]
// block = 256 threads (8 warps), handles 8 consecutive t of one b
// ---------------------------------------------------------------------------
__global__ void prep_encproj(const float* __restrict__ enc,
                             const float* __restrict__ W_enc) {
    __shared__ float se[8 * ED];  // 8 rows of 256
    int bt0 = blockIdx.x * 8;
    int b = bt0 / TE, t0 = bt0 % TE;
    int tid = threadIdx.x, w = tid >> 5, l = tid & 31;

    const float4* src = (const float4*)(enc + ((size_t)b * TE + t0) * ED);
    for (int i = tid; i < 8 * ED / 4; i += 256) ((float4*)se)[i] = src[i];
    __syncthreads();

    for (int a = w; a < AD; a += 8) {
        const float* wr = W_enc + (size_t)a * ED;
        float4 q0 = *(const float4*)(wr + 4 * l);
        float4 q1 = *(const float4*)(wr + 128 + 4 * l);
        #pragma unroll
        for (int tt = 0; tt < 8; ++tt) {
            float4 e0 = *(const float4*)(se + tt * ED + 4 * l);
            float4 e1 = *(const float4*)(se + tt * ED + 128 + 4 * l);
            float acc = dot4(q0, e0) + dot4(q1, e1);
            acc = wsum(acc);
            if (l == 0) g_ep[((size_t)b * TE + t0 + tt) * AD + a] = acc;
        }
    }
}

// ---------------------------------------------------------------------------
// P2: transpose enc_feat (b,t,e) -> (b,e,t)
// ---------------------------------------------------------------------------
__global__ void prep_transpose(const float* __restrict__ enc) {
    __shared__ float tile[32][33];
    int b = blockIdx.z;
    int t0 = blockIdx.x * 32, e0 = blockIdx.y * 32;
    int tx = threadIdx.x, ty = threadIdx.y;
    #pragma unroll
    for (int k = 0; k < 4; ++k)
        tile[ty + 8 * k][tx] = enc[((size_t)b * TE + t0 + ty + 8 * k) * ED + e0 + tx];
    __syncthreads();
    #pragma unroll
    for (int k = 0; k < 4; ++k)
        g_encT[((size_t)b * ED + e0 + ty + 8 * k) * TE + t0 + tx] = tile[tx][ty + 8 * k];
}

// ---------------------------------------------------------------------------
// P3: gix[b][t][r] = sum_{j<80} W_ih[r][j]*gt[b][t][j] + folded bias
//   r < 512 : + b_ih[r] + b_hh[r]   (r,z pre-activations take both biases)
//   r >= 512: + b_ih[r]             (n-gate keeps b_hh with the hh dot)
// block = 256 threads (8 warps), 8 consecutive t of one b
// ---------------------------------------------------------------------------
__global__ void prep_gix(const float* __restrict__ gt,
                         const float* __restrict__ W_ih,
                         const float* __restrict__ b_ih,
                         const float* __restrict__ b_hh) {
    __shared__ float sx[8 * ID];  // 640 floats, contiguous rows
    int bt0 = blockIdx.x * 8;
    int b = bt0 / TD, t0 = bt0 % TD;
    int tid = threadIdx.x, w = tid >> 5, l = tid & 31;

    const float* src = gt + ((size_t)b * TD + t0) * ID;
    for (int i = tid; i < 8 * ID; i += 256) sx[i] = src[i];
    __syncthreads();

    for (int r = w; r < 768; r += 8) {
        float4 wf = make_float4(0.f, 0.f, 0.f, 0.f);
        if (l < 20) wf = *(const float4*)(W_ih + (size_t)r * 336 + 4 * l);
        #pragma unroll
        for (int tt = 0; tt < 8; ++tt) {
            float acc = 0.f;
            if (l < 20) {
                float4 xf = *(const float4*)(sx + tt * ID + 4 * l);
                acc = dot4(wf, xf);
            }
            acc = wsum(acc);
            if (l == 0) {
                float bias = (r < 512) ? (b_ih[r] + b_hh[r]) : b_ih[r];
                g_gix[((size_t)b * TD + t0 + tt) * 768 + r] = acc + bias;
            }
        }
    }
}

// ---------------------------------------------------------------------------
// Decoder: one CTA per batch element, 1024 threads, 400 sequential steps
// ---------------------------------------------------------------------------
__global__ void __launch_bounds__(1024, 1)
decoder_kernel(const float* __restrict__ W_dec,
               const float* __restrict__ b_attn,
               const float* __restrict__ v_attn,
               const float* __restrict__ b_hh,
               const float* __restrict__ b_out,
               float* __restrict__ out) {
    const int b = blockIdx.x;
    const int tid = threadIdx.x, w = tid >> 5, l = tid & 31;

    __shared__ float sh_in[512];    // [ctx(256) ; h(256)]
    __shared__ float sh_gA[512];    // r,z pre-activations (with gix folded)
    __shared__ float sh_gBC[512];   // [0..255]: gi_n (ctx part + gix), [256..511]: raw hh dot
    __shared__ float sh_dp[128];
    __shared__ float sh_s[800];     // scores -> exp -> normalized attn
    __shared__ float sh_o[80];
    __shared__ float sh_red[32];
    __shared__ float sh_m[2];

    if (tid < 512) sh_in[tid] = 0.f;

    const float4 vf = *(const float4*)(v_attn + 4 * l);   // v_attn slice, step-invariant
    const float* ep_b = g_ep + (size_t)b * TE * AD;
    const float* eT_b = g_encT + (size_t)b * ED * TE;
    const size_t attn_base = (size_t)BB * TD * ID;        // pred block size
    __syncthreads();

    for (int t = 0; t < TD; ++t) {
        const float* gix = g_gix + ((size_t)b * TD + t) * 768;

        // hoist input vector [ctx ; h] (previous step's values)
        float4 in0 = *(const float4*)(sh_in + 4 * l);
        float4 in1 = *(const float4*)(sh_in + 128 + 4 * l);
        float4 in2 = *(const float4*)(sh_in + 256 + 4 * l);
        float4 in3 = *(const float4*)(sh_in + 384 + 4 * l);

        // ---- GRU phase A: 512 rows x dot(512) for r,z -------------------
        #pragma unroll 2
        for (int i = 0; i < 16; ++i) {
            int r = w * 16 + i;
            const float* wr = g_WA + (size_t)r * 512;
            float4 a0 = *(const float4*)(wr + 4 * l);
            float4 a1 = *(const float4*)(wr + 128 + 4 * l);
            float4 a2 = *(const float4*)(wr + 256 + 4 * l);
            float4 a3 = *(const float4*)(wr + 384 + 4 * l);
            float acc = dot4(a0, in0) + dot4(a1, in1) + dot4(a2, in2) + dot4(a3, in3);
            acc = wsum(acc);
            if (l == 0) sh_gA[r] = acc + gix[r];
        }
        // ---- GRU phase B: n-gate ctx-dot (256 rows) + hh-dot (256 rows) -
        #pragma unroll 2
        for (int i = 0; i < 16; ++i) {
            int j = w * 16 + i;
            float acc;
            if (j < 256) {
                const float* wr = g_WB + (size_t)j * 256;
                float4 a0 = *(const float4*)(wr + 4 * l);
                float4 a1 = *(const float4*)(wr + 128 + 4 * l);
                acc = dot4(a0, in0) + dot4(a1, in1);
            } else {
                const float* wr = g_WC + (size_t)(j - 256) * 256;
                float4 a0 = *(const float4*)(wr + 4 * l);
                float4 a1 = *(const float4*)(wr + 128 + 4 * l);
                acc = dot4(a0, in2) + dot4(a1, in3);
            }
            acc = wsum(acc);
            if (l == 0) sh_gBC[j] = (j < 256) ? (acc + gix[512 + j]) : acc;
        }
        __syncthreads();

        // ---- gates (precise math; only 256 evals) -----------------------
        if (tid < 256) {
            int i = tid;
            float r = 1.f / (1.f + __expf(-sh_gA[i]));
            float z = 1.f / (1.f + __expf(-sh_gA[256 + i]));
            float hn = sh_gBC[256 + i] + b_hh[512 + i];
            float n = tanhf(fmaf(r, hn, sh_gBC[i]));
            float ho = sh_in[256 + i];
            sh_in[256 + i] = fmaf(z, ho - n, n);   // (1-z)*n + z*h
        }
        __syncthreads();

        // ---- dec_proj: 128 rows x dot(256) on h_new ---------------------
        {
            float4 h0 = *(const float4*)(sh_in + 256 + 4 * l);
            float4 h1 = *(const float4*)(sh_in + 384 + 4 * l);
            #pragma unroll
            for (int i = 0; i < 4; ++i) {
                int a = w * 4 + i;
                const float* wr = W_dec + (size_t)a * 256;
                float4 d0 = *(const float4*)(wr + 4 * l);
                float4 d1 = *(const float4*)(wr + 128 + 4 * l);
                float acc = dot4(d0, h0) + dot4(d1, h1);
                acc = wsum(acc);
                if (l == 0) sh_dp[a] = acc + b_attn[a];
            }
        }
        __syncthreads();

        // ---- attention scores: 800 x (128-dim tanh dot), MUFU tanh ------
        {
            float4 dp = *(const float4*)(sh_dp + 4 * l);
            #pragma unroll 2
            for (int i = 0; i < 25; ++i) {
                int tt = w * 25 + i;
                float4 ep = *(const float4*)(ep_b + (size_t)tt * AD + 4 * l);
                float s = vf.x * ftanh(ep.x + dp.x);
                s = fmaf(vf.y, ftanh(ep.y + dp.y), s);
                s = fmaf(vf.z, ftanh(ep.z + dp.z), s);
                s = fmaf(vf.w, ftanh(ep.w + dp.w), s);
                s = wsum(s);
                if (l == 0) sh_s[tt] = s;
            }
        }
        __syncthreads();

        // ---- softmax over 800 ------------------------------------------
        float sv = (tid < 800) ? sh_s[tid] : -1e30f;
        float pm = wmaxr(sv);
        if (l == 0) sh_red[w] = pm;
        __syncthreads();
        if (w == 0) { float v2 = wmaxr(sh_red[l]); if (l == 0) sh_m[0] = v2; }
        __syncthreads();
        float m = sh_m[0];
        float ev = 0.f;
        if (tid < 800) { ev = __expf(sh_s[tid] - m); sh_s[tid] = ev; }
        float ps = wsum(ev);
        if (l == 0) sh_red[w] = ps;
        __syncthreads();
        if (w == 0) { float v2 = wsum(sh_red[l]); if (l == 0) sh_m[1] = v2; }
        __syncthreads();
        float inv = 1.f / sh_m[1];
        if (tid < 800) {
            float a = ev * inv;
            sh_s[tid] = a;
            out[attn_base + ((size_t)b * TD + t) * TE + tid] = a;
        }
        __syncthreads();

        // ---- ctx: ctx[e] = sum_t attn[t] * encT[e][t] -------------------
        {
            float4 pf[7];
            #pragma unroll
            for (int k = 0; k < 6; ++k) pf[k] = *(const float4*)(sh_s + 4 * (l + 32 * k));
            if (l < 8) pf[6] = *(const float4*)(sh_s + 768 + 4 * l);
            #pragma unroll
            for (int j = 0; j < 8; ++j) {
                int e = w * 8 + j;
                const float* er = eT_b + (size_t)e * TE;
                float acc = 0.f;
                #pragma unroll
                for (int k = 0; k < 6; ++k) {
                    float4 ev4 = *(const float4*)(er + 4 * (l + 32 * k));
                    acc += dot4(ev4, pf[k]);
                }
                if (l < 8) {
                    float4 ev4 = *(const float4*)(er + 768 + 4 * l);
                    acc += dot4(ev4, pf[6]);
                }
                acc = wsum(acc);
                if (l == 0) sh_in[e] = acc;   // new ctx
            }
        }
        __syncthreads();

        // ---- output logits: 80 rows x dot(512) on [ctx ; h] -------------
        {
            float4 c0 = *(const float4*)(sh_in + 4 * l);
            float4 c1 = *(const float4*)(sh_in + 128 + 4 * l);
            float4 c2 = *(const float4*)(sh_in + 256 + 4 * l);
            float4 c3 = *(const float4*)(sh_in + 384 + 4 * l);
            for (int o = w; o < 80; o += 32) {
                const float* wr = g_WO + (size_t)o * 512;
                float4 a0 = *(const float4*)(wr + 4 * l);
                float4 a1 = *(const float4*)(wr + 128 + 4 * l);
                float4 a2 = *(const float4*)(wr + 256 + 4 * l);
                float4 a3 = *(const float4*)(wr + 384 + 4 * l);
                float acc = dot4(a0, c0) + dot4(a1, c1) + dot4(a2, c2) + dot4(a3, c3);
                acc = wsum(acc);
                if (l == 0) sh_o[o] = acc + b_out[o];
            }
        }
        __syncthreads();

        // ---- log_softmax(80) + write pred (warp 0; others run ahead) ----
        if (w == 0) {
            float v0 = sh_o[l];
            float v1 = sh_o[32 + l];
            float v2 = (l < 16) ? sh_o[64 + l] : -1e30f;
            float mm = wallmax(fmaxf(fmaxf(v0, v1), v2));
            float se = __expf(v0 - mm) + __expf(v1 - mm) +
                       ((l < 16) ? __expf(v2 - mm) : 0.f);
            se = wallsum(se);
            float ls = mm + logf(se);
            float* pr = out + ((size_t)b * TD + t) * ID;
            pr[l] = v0 - ls;
            pr[32 + l] = v1 - ls;
            if (l < 16) pr[64 + l] = v2 - ls;
        }
        // no trailing sync needed: next-iteration writers/readers are
        // separated by the phase-A -> gates __syncthreads.
    }
}

// ---------------------------------------------------------------------------
// Launch
// ---------------------------------------------------------------------------
extern "C" void kernel_launch(void* const* d_in, const int* in_sizes, int n_in,
                              void* d_out, int out_size) {
    const float* enc    = (const float*)d_in[0];
    const float* gt     = (const float*)d_in[1];
    const float* W_ih   = (const float*)d_in[2];
    const float* W_hh   = (const float*)d_in[3];
    const float* b_ih   = (const float*)d_in[4];
    const float* b_hh   = (const float*)d_in[5];
    const float* W_enc  = (const float*)d_in[6];
    const float* W_dec  = (const float*)d_in[7];
    const float* b_attn = (const float*)d_in[8];
    const float* v_attn = (const float*)d_in[9];
    const float* W_out  = (const float*)d_in[10];
    const float* b_out  = (const float*)d_in[11];
    float* out = (float*)d_out;

    prep_repack<<<256, 256>>>(W_ih, W_hh, W_out);
    prep_encproj<<<BB * TE / 8, 256>>>(enc, W_enc);
    prep_transpose<<<dim3(TE / 32, ED / 32, BB), dim3(32, 8)>>>(enc);
    prep_gix<<<BB * TD / 8, 256>>>(gt, W_ih, b_ih, b_hh);
    decoder_kernel<<<BB, 1024>>>(W_dec, b_attn, v_attn, b_hh, b_out, out);
}

// round 12
// speedup vs baseline: 2.3808x; 2.3808x over previous
#include <cuda_runtime.h>
#include <cuda_bf16.h>
#include <cstdint>

// Problem dims
#define BB 32     // batch
#define TE 800    // encoder timesteps
#define TD 400    // decoder timesteps
#define ED 256    // encoder feature dim
#define AD 128    // attention dim
#define GD 256    // GRU dim
#define ID 80     // input dim

// ---------------------------------------------------------------------------
// Scratch (__device__ globals)
// ---------------------------------------------------------------------------
__device__ float g_ep[(size_t)BB * TE * AD];              // enc_proj (b,t,a) fp32
__device__ __nv_bfloat16 g_encTh[(size_t)BB * ED * TE];   // enc transposed (b,e,t) bf16
__device__ float g_gix[(size_t)BB * TD * 768];            // x-part GRU preacts + folded biases
__device__ float g_WG[256 * 1536];                        // per-i packed GRU weights:
                                                          // [Wr(512)|Wz(512)|Wn_ctx(256)|Wn_h(256)]
__device__ float g_WO[80 * 512];                          // W_out permuted to [ctx|h]

// ---------------------------------------------------------------------------
// Helpers
// ---------------------------------------------------------------------------
__device__ __forceinline__ float dot4(float4 a, float4 b) {
    return fmaf(a.x, b.x, fmaf(a.y, b.y, fmaf(a.z, b.z, a.w * b.w)));
}
__device__ __forceinline__ float wsum(float v) {
    v += __shfl_down_sync(0xffffffffu, v, 16);
    v += __shfl_down_sync(0xffffffffu, v, 8);
    v += __shfl_down_sync(0xffffffffu, v, 4);
    v += __shfl_down_sync(0xffffffffu, v, 2);
    v += __shfl_down_sync(0xffffffffu, v, 1);
    return v;  // lane 0 valid
}
__device__ __forceinline__ float wallmax(float v) {
    #pragma unroll
    for (int s = 16; s > 0; s >>= 1) v = fmaxf(v, __shfl_xor_sync(0xffffffffu, v, s));
    return v;
}
__device__ __forceinline__ float wallsum(float v) {
    #pragma unroll
    for (int s = 16; s > 0; s >>= 1) v += __shfl_xor_sync(0xffffffffu, v, s);
    return v;
}
__device__ __forceinline__ float ftanh(float x) {
    float y;
    asm("tanh.approx.f32 %0, %1;" : "=f"(y) : "f"(x));
    return y;
}
__device__ __forceinline__ uint32_t smem_u32(const void* p) {
    uint32_t a;
    asm("{ .reg .u64 t; cvta.to.shared.u64 t, %1; cvt.u32.u64 %0, t; }" : "=r"(a) : "l"(p));
    return a;
}
__device__ __forceinline__ void st_cluster(uint32_t laddr, uint32_t rank, float v) {
    uint32_t ra;
    asm volatile("mapa.shared::cluster.u32 %0, %1, %2;" : "=r"(ra) : "r"(laddr), "r"(rank));
    asm volatile("st.shared::cluster.f32 [%0], %1;" :: "r"(ra), "f"(v) : "memory");
}
__device__ __forceinline__ void bcast4(const void* p, float v) {
    uint32_t la = smem_u32(p);
    #pragma unroll
    for (uint32_t r = 0; r < 4; ++r) st_cluster(la, r, v);
}
__device__ __forceinline__ void cluster_sync() {
    asm volatile("barrier.cluster.arrive.aligned;" ::: "memory");
    asm volatile("barrier.cluster.wait.aligned;" ::: "memory");
}

// ---------------------------------------------------------------------------
// prep_repack: build g_WG (per-i contiguous GRU rows) and g_WO ([ctx|h])
// ---------------------------------------------------------------------------
__global__ void prep_repack(const float* __restrict__ W_ih,
                            const float* __restrict__ W_hh,
                            const float* __restrict__ W_out) {
    int stride = gridDim.x * blockDim.x;
    int g = blockIdx.x * blockDim.x + threadIdx.x;
    for (int idx = g; idx < 256 * 1536; idx += stride) {
        int i = idx / 1536, c = idx % 1536;
        int seg = c >> 8, cc = c & 255;
        float v;
        switch (seg) {
            case 0:  v = W_ih[(size_t)i * 336 + 80 + cc]; break;          // r gate, ctx cols
            case 1:  v = W_hh[(size_t)i * 256 + cc]; break;               // r gate, h cols
            case 2:  v = W_ih[(size_t)(256 + i) * 336 + 80 + cc]; break;  // z gate, ctx
            case 3:  v = W_hh[(size_t)(256 + i) * 256 + cc]; break;       // z gate, h
            case 4:  v = W_ih[(size_t)(512 + i) * 336 + 80 + cc]; break;  // n gate, ctx
            default: v = W_hh[(size_t)(512 + i) * 256 + cc]; break;       // n gate, h
        }
        g_WG[idx] = v;
    }
    for (int idx = g; idx < 80 * 512; idx += stride) {
        int r = idx >> 9, c = idx & 511;
        g_WO[idx] = (c < 256) ? W_out[(size_t)r * 512 + 256 + c]
                              : W_out[(size_t)r * 512 + (c - 256)];
    }
}

// ---------------------------------------------------------------------------
// prep_encproj: g_ep[m][a] = enc[m][:] . W_enc[a][:]   (M=25600, K=256, N=128)
// block: 16 rows of m; 256 threads = 128 a x 2 halves; 8 outputs/thread
// ---------------------------------------------------------------------------
__global__ void __launch_bounds__(256) prep_encproj(const float* __restrict__ enc,
                                                    const float* __restrict__ W_enc) {
    __shared__ float x[16 * ED];
    int m0 = blockIdx.x * 16;
    int tid = threadIdx.x;
    const float4* src = (const float4*)(enc + (size_t)m0 * ED);
    float4* xd = (float4*)x;
    #pragma unroll
    for (int q = 0; q < 4; ++q) xd[tid + 256 * q] = src[tid + 256 * q];
    __syncthreads();

    int a = tid & 127, half = tid >> 7;
    const float4* wr = (const float4*)(W_enc + (size_t)a * ED);
    float acc[8] = {0.f, 0.f, 0.f, 0.f, 0.f, 0.f, 0.f, 0.f};
    for (int k4 = 0; k4 < 64; ++k4) {
        float4 wv = wr[k4];
        #pragma unroll
        for (int i = 0; i < 8; ++i) {
            float4 xv = xd[(8 * half + i) * 64 + k4];   // broadcast within warp
            acc[i] += dot4(wv, xv);
        }
    }
    #pragma unroll
    for (int i = 0; i < 8; ++i)
        g_ep[(size_t)(m0 + 8 * half + i) * AD + a] = acc[i];
}

// ---------------------------------------------------------------------------
// prep_transpose: enc (b,t,e) fp32 -> g_encTh (b,e,t) bf16
// ---------------------------------------------------------------------------
__global__ void prep_transpose(const float* __restrict__ enc) {
    __shared__ float tile[32][33];
    int b = blockIdx.z;
    int t0 = blockIdx.x * 32, e0 = blockIdx.y * 32;
    int tx = threadIdx.x, ty = threadIdx.y;
    #pragma unroll
    for (int k = 0; k < 4; ++k)
        tile[ty + 8 * k][tx] = enc[((size_t)b * TE + t0 + ty + 8 * k) * ED + e0 + tx];
    __syncthreads();
    #pragma unroll
    for (int k = 0; k < 4; ++k)
        g_encTh[((size_t)b * ED + e0 + ty + 8 * k) * TE + t0 + tx] =
            __float2bfloat16(tile[tx][ty + 8 * k]);
}

// ---------------------------------------------------------------------------
// prep_gix: g_gix[m][r] = gt[m][:80] . W_ih[r][:80] + folded bias
// block: 8 rows of m; thread handles 3 r-values x 8 m each
// ---------------------------------------------------------------------------
__global__ void __launch_bounds__(256) prep_gix(const float* __restrict__ gt,
                                                const float* __restrict__ W_ih,
                                                const float* __restrict__ b_ih,
                                                const float* __restrict__ b_hh) {
    __shared__ float x[8 * ID];
    int m0 = blockIdx.x * 8;
    int tid = threadIdx.x;
    if (tid < 160) ((float4*)x)[tid] = ((const float4*)(gt + (size_t)m0 * ID))[tid];
    __syncthreads();

    #pragma unroll
    for (int j = 0; j < 3; ++j) {
        int r = 256 * j + tid;
        const float* wr = W_ih + (size_t)r * 336;
        float acc[8] = {0.f, 0.f, 0.f, 0.f, 0.f, 0.f, 0.f, 0.f};
        #pragma unroll 4
        for (int k4 = 0; k4 < 20; ++k4) {
            float4 wv = *(const float4*)(wr + 4 * k4);
            #pragma unroll
            for (int i = 0; i < 8; ++i) {
                float4 xv = ((float4*)x)[i * 20 + k4];   // broadcast
                acc[i] += dot4(wv, xv);
            }
        }
        float bias = (r < 512) ? (b_ih[r] + b_hh[r]) : b_ih[r];
        #pragma unroll
        for (int i = 0; i < 8; ++i)
            g_gix[(size_t)(m0 + i) * 768 + r] = acc[i] + bias;
    }
}

// ---------------------------------------------------------------------------
// Decoder: 4-CTA cluster per batch element, 1024 threads/CTA, grid 128
// CTA rank rk owns: gates i in [64rk,64rk+64), dp rows [32rk,+32),
// scores t in [200rk,+200), ctx e in [64rk,+64), logits o in [20rk,+20)
// State replicated in every CTA's SMEM via DSMEM broadcasts.
// ---------------------------------------------------------------------------
struct SMem {
    float buf[2][512];   // ping-pong [ctx(256);h(256)]
    float attn[800];     // exp(scores), unnormalized
    float dp[128];
    float o[80];
    float pre[4][64];    // local gate partials: r,z,n_ctx,n_h
    float red[32];
    float misc[4];
};

__global__ void __launch_bounds__(1024, 1) __cluster_dims__(4, 1, 1)
decoder_kernel(const float* __restrict__ W_dec,
               const float* __restrict__ b_attn,
               const float* __restrict__ v_attn,
               const float* __restrict__ b_hh,
               const float* __restrict__ b_out,
               float* __restrict__ out) {
    __shared__ SMem sm;
    const int b = blockIdx.x >> 2;
    uint32_t rk;
    asm("mov.u32 %0, %%cluster_ctarank;" : "=r"(rk));
    const int tid = threadIdx.x, w = tid >> 5, l = tid & 31;

    if (tid < 512) sm.buf[0][tid] = 0.f;
    const float4 vf = *(const float4*)(v_attn + 4 * l);
    const float* ep_b = g_ep + (size_t)b * TE * AD;
    const __nv_bfloat16* eT_b = g_encTh + (size_t)b * ED * TE;
    const size_t attn_base = (size_t)BB * TD * ID;
    __syncthreads();
    cluster_sync();

    int p = 0;
    for (int t = 0; t < TD; ++t) {
        const float* gix = g_gix + ((size_t)b * TD + t) * 768;

        float4 in0 = *(const float4*)(sm.buf[p] + 4 * l);
        float4 in1 = *(const float4*)(sm.buf[p] + 128 + 4 * l);
        float4 in2 = *(const float4*)(sm.buf[p] + 256 + 4 * l);
        float4 in3 = *(const float4*)(sm.buf[p] + 384 + 4 * l);

        // ---- GRU: each warp computes all 4 dots for 2 hidden units ------
        #pragma unroll
        for (int ii = 0; ii < 2; ++ii) {
            int il = w * 2 + ii;
            int ig = 64 * (int)rk + il;
            const float* wr = g_WG + (size_t)ig * 1536;
            float4 a0 = *(const float4*)(wr + 4 * l);
            float4 a1 = *(const float4*)(wr + 128 + 4 * l);
            float4 a2 = *(const float4*)(wr + 256 + 4 * l);
            float4 a3 = *(const float4*)(wr + 384 + 4 * l);
            float accR = dot4(a0, in0) + dot4(a1, in1) + dot4(a2, in2) + dot4(a3, in3);
            float4 z0 = *(const float4*)(wr + 512 + 4 * l);
            float4 z1 = *(const float4*)(wr + 640 + 4 * l);
            float4 z2 = *(const float4*)(wr + 768 + 4 * l);
            float4 z3 = *(const float4*)(wr + 896 + 4 * l);
            float accZ = dot4(z0, in0) + dot4(z1, in1) + dot4(z2, in2) + dot4(z3, in3);
            float4 n0 = *(const float4*)(wr + 1024 + 4 * l);
            float4 n1 = *(const float4*)(wr + 1152 + 4 * l);
            float accB = dot4(n0, in0) + dot4(n1, in1);
            float4 h0 = *(const float4*)(wr + 1280 + 4 * l);
            float4 h1 = *(const float4*)(wr + 1408 + 4 * l);
            float accC = dot4(h0, in2) + dot4(h1, in3);
            accR = wsum(accR); accZ = wsum(accZ);
            accB = wsum(accB); accC = wsum(accC);
            if (l == 0) {
                sm.pre[0][il] = accR + gix[ig];
                sm.pre[1][il] = accZ + gix[256 + ig];
                sm.pre[2][il] = accB + gix[512 + ig];
                sm.pre[3][il] = accC;
            }
        }
        __syncthreads();
        if (tid < 64) {
            int ig = 64 * (int)rk + tid;
            float r = 1.f / (1.f + __expf(-sm.pre[0][tid]));
            float z = 1.f / (1.f + __expf(-sm.pre[1][tid]));
            float hn = sm.pre[3][tid] + b_hh[512 + ig];
            float n = tanhf(fmaf(r, hn, sm.pre[2][tid]));
            float ho = sm.buf[p][256 + ig];
            bcast4(&sm.buf[p ^ 1][256 + ig], fmaf(z, ho - n, n));
        }
        cluster_sync();  // #1: h_new visible everywhere

        // ---- dec_proj: one row per warp ---------------------------------
        {
            float4 h0 = *(const float4*)(sm.buf[p ^ 1] + 256 + 4 * l);
            float4 h1 = *(const float4*)(sm.buf[p ^ 1] + 384 + 4 * l);
            int a = 32 * (int)rk + w;
            const float* wr = W_dec + (size_t)a * 256;
            float4 d0 = *(const float4*)(wr + 4 * l);
            float4 d1 = *(const float4*)(wr + 128 + 4 * l);
            float acc = dot4(d0, h0) + dot4(d1, h1);
            acc = wsum(acc);
            if (l == 0) bcast4(&sm.dp[a], acc + b_attn[a]);
        }
        cluster_sync();  // #2: dp visible

        // ---- scores: exp(v . tanh(ep + dp)) for this CTA's 200 t --------
        {
            float4 dp = *(const float4*)(sm.dp + 4 * l);
            for (int tt = w; tt < 200; tt += 32) {
                int tg = 200 * (int)rk + tt;
                float4 ep = *(const float4*)(ep_b + (size_t)tg * AD + 4 * l);
                float s = vf.x * ftanh(ep.x + dp.x);
                s = fmaf(vf.y, ftanh(ep.y + dp.y), s);
                s = fmaf(vf.z, ftanh(ep.z + dp.z), s);
                s = fmaf(vf.w, ftanh(ep.w + dp.w), s);
                s = wsum(s);
                if (l == 0) bcast4(&sm.attn[tg], __expf(s));  // |s| <= ~5, safe
            }
        }
        cluster_sync();  // #3: all 800 exp-scores visible

        // ---- normalizer (redundant per CTA) + attn output ---------------
        float sv = (tid < 800) ? sm.attn[tid] : 0.f;
        sv = wsum(sv);
        if (l == 0) sm.red[w] = sv;
        __syncthreads();
        if (w == 0) {
            float v2 = wsum(sm.red[l]);
            if (l == 0) sm.misc[0] = 1.f / v2;
        }
        __syncthreads();
        float inv = sm.misc[0];
        if (tid < 200) {
            int tg = 200 * (int)rk + tid;
            out[attn_base + ((size_t)b * TD + t) * TE + tg] = sm.attn[tg] * inv;
        }

        // ---- ctx: 2 e per warp, bf16 encT, dot over 800 -----------------
        #pragma unroll
        for (int j = 0; j < 2; ++j) {
            int e = 64 * (int)rk + w + 32 * j;
            const __nv_bfloat16* er = eT_b + (size_t)e * TE;
            float acc = 0.f;
            #pragma unroll
            for (int k = 0; k < 12; ++k) {
                int tt = 2 * (l + 32 * k);
                float2 ev = __bfloat1622float2(*(const __nv_bfloat162*)(er + tt));
                float2 av = *(const float2*)(sm.attn + tt);
                acc = fmaf(ev.x, av.x, fmaf(ev.y, av.y, acc));
            }
            if (l < 16) {
                int tt = 768 + 2 * l;
                float2 ev = __bfloat1622float2(*(const __nv_bfloat162*)(er + tt));
                float2 av = *(const float2*)(sm.attn + tt);
                acc = fmaf(ev.x, av.x, fmaf(ev.y, av.y, acc));
            }
            acc = wsum(acc);
            if (l == 0) bcast4(&sm.buf[p ^ 1][e], acc * inv);
        }
        cluster_sync();  // #4: ctx visible

        // ---- output logits: 20 rows per CTA, sent to rank 0 -------------
        {
            float4 c0 = *(const float4*)(sm.buf[p ^ 1] + 4 * l);
            float4 c1 = *(const float4*)(sm.buf[p ^ 1] + 128 + 4 * l);
            float4 c2 = *(const float4*)(sm.buf[p ^ 1] + 256 + 4 * l);
            float4 c3 = *(const float4*)(sm.buf[p ^ 1] + 384 + 4 * l);
            if (w < 20) {
                int og = 20 * (int)rk + w;
                const float* wr = g_WO + (size_t)og * 512;
                float4 a0 = *(const float4*)(wr + 4 * l);
                float4 a1 = *(const float4*)(wr + 128 + 4 * l);
                float4 a2 = *(const float4*)(wr + 256 + 4 * l);
                float4 a3 = *(const float4*)(wr + 384 + 4 * l);
                float acc = dot4(a0, c0) + dot4(a1, c1) + dot4(a2, c2) + dot4(a3, c3);
                acc = wsum(acc);
                if (l == 0) st_cluster(smem_u32(&sm.o[og]), 0, acc + b_out[og]);
            }
        }
        cluster_sync();  // #5: logits at rank 0; also step boundary

        if (rk == 0 && w == 0) {
            float v0 = sm.o[l];
            float v1 = sm.o[32 + l];
            float v2 = (l < 16) ? sm.o[64 + l] : -1e30f;
            float mm = wallmax(fmaxf(fmaxf(v0, v1), v2));
            float se = __expf(v0 - mm) + __expf(v1 - mm) +
                       ((l < 16) ? __expf(v2 - mm) : 0.f);
            se = wallsum(se);
            float ls = mm + logf(se);
            float* pr = out + ((size_t)b * TD + t) * ID;
            pr[l] = v0 - ls;
            pr[32 + l] = v1 - ls;
            if (l < 16) pr[64 + l] = v2 - ls;
        }
        p ^= 1;
    }
}

// ---------------------------------------------------------------------------
// Launch
// ---------------------------------------------------------------------------
extern "C" void kernel_launch(void* const* d_in, const int* in_sizes, int n_in,
                              void* d_out, int out_size) {
    const float* enc    = (const float*)d_in[0];
    const float* gt     = (const float*)d_in[1];
    const float* W_ih   = (const float*)d_in[2];
    const float* W_hh   = (const float*)d_in[3];
    const float* b_ih   = (const float*)d_in[4];
    const float* b_hh   = (const float*)d_in[5];
    const float* W_enc  = (const float*)d_in[6];
    const float* W_dec  = (const float*)d_in[7];
    const float* b_attn = (const float*)d_in[8];
    const float* v_attn = (const float*)d_in[9];
    const float* W_out  = (const float*)d_in[10];
    const float* b_out  = (const float*)d_in[11];
    float* out = (float*)d_out;

    prep_repack<<<256, 256>>>(W_ih, W_hh, W_out);
    prep_encproj<<<BB * TE / 16, 256>>>(enc, W_enc);
    prep_transpose<<<dim3(TE / 32, ED / 32, BB), dim3(32, 8)>>>(enc);
    prep_gix<<<BB * TD / 8, 256>>>(gt, W_ih, b_ih, b_hh);
    decoder_kernel<<<BB * 4, 1024>>>(W_dec, b_attn, v_attn, b_hh, b_out, out);
}

// round 16
// speedup vs baseline: 2.6025x; 1.0931x over previous
#include <cuda_runtime.h>
#include <cuda_fp16.h>
#include <cstdint>

// Problem dims
#define BB 32     // batch
#define TE 800    // encoder timesteps
#define TD 400    // decoder timesteps
#define ED 256    // encoder feature dim
#define AD 128    // attention dim
#define GD 256    // GRU dim
#define ID 80     // input dim

// ---------------------------------------------------------------------------
// Scratch (__device__ globals)
// ---------------------------------------------------------------------------
__device__ __half g_eph[(size_t)BB * TE * AD];    // enc_proj (b,t,a) fp16
__device__ __half g_encTh[(size_t)BB * ED * TE];  // enc transposed (b,e,t) fp16
__device__ float  g_gix[(size_t)BB * TD * 768];   // x-part GRU preacts + folded biases (fp32)
__device__ __half g_WGh[256 * 1536];              // per-i packed GRU weights fp16:
                                                  // [Wr(512)|Wz(512)|Wn_ctx(256)|Wn_h(256)]
__device__ __half g_WOh[80 * 512];                // W_out permuted to [ctx|h], fp16
__device__ __half g_Wdh[128 * 256];               // W_dec fp16

// ---------------------------------------------------------------------------
// Helpers
// ---------------------------------------------------------------------------
__device__ __forceinline__ float dot4(float4 a, float4 b) {
    return fmaf(a.x, b.x, fmaf(a.y, b.y, fmaf(a.z, b.z, a.w * b.w)));
}
__device__ __forceinline__ float4 h4tof4(uint2 u) {
    __half2 a = *reinterpret_cast<__half2*>(&u.x);
    __half2 b = *reinterpret_cast<__half2*>(&u.y);
    float2 fa = __half22float2(a), fb = __half22float2(b);
    return make_float4(fa.x, fa.y, fb.x, fb.y);
}
__device__ __forceinline__ void h8tof8(uint4 u, float4& A, float4& B) {
    A = h4tof4(make_uint2(u.x, u.y));
    B = h4tof4(make_uint2(u.z, u.w));
}
__device__ __forceinline__ float wsum(float v) {
    v += __shfl_down_sync(0xffffffffu, v, 16);
    v += __shfl_down_sync(0xffffffffu, v, 8);
    v += __shfl_down_sync(0xffffffffu, v, 4);
    v += __shfl_down_sync(0xffffffffu, v, 2);
    v += __shfl_down_sync(0xffffffffu, v, 1);
    return v;  // lane 0 valid
}
__device__ __forceinline__ float wallmax(float v) {
    #pragma unroll
    for (int s = 16; s > 0; s >>= 1) v = fmaxf(v, __shfl_xor_sync(0xffffffffu, v, s));
    return v;
}
__device__ __forceinline__ float wallsum(float v) {
    #pragma unroll
    for (int s = 16; s > 0; s >>= 1) v += __shfl_xor_sync(0xffffffffu, v, s);
    return v;
}
__device__ __forceinline__ float ftanh(float x) {
    float y;
    asm("tanh.approx.f32 %0, %1;" : "=f"(y) : "f"(x));
    return y;
}
__device__ __forceinline__ uint32_t smem_u32(const void* p) {
    uint32_t a;
    asm("{ .reg .u64 t; cvta.to.shared.u64 t, %1; cvt.u32.u64 %0, t; }" : "=r"(a) : "l"(p));
    return a;
}
__device__ __forceinline__ void st_cluster(uint32_t laddr, uint32_t rank, float v) {
    uint32_t ra;
    asm volatile("mapa.shared::cluster.u32 %0, %1, %2;" : "=r"(ra) : "r"(laddr), "r"(rank));
    asm volatile("st.shared::cluster.f32 [%0], %1;" :: "r"(ra), "f"(v) : "memory");
}
__device__ __forceinline__ void bcast4(const void* p, float v) {
    uint32_t la = smem_u32(p);
    #pragma unroll
    for (uint32_t r = 0; r < 4; ++r) st_cluster(la, r, v);
}
__device__ __forceinline__ void cluster_sync() {
    asm volatile("barrier.cluster.arrive.aligned;" ::: "memory");
    asm volatile("barrier.cluster.wait.aligned;" ::: "memory");
}

// ---------------------------------------------------------------------------
// prep_repack: build g_WGh (per-i contiguous GRU rows), g_WOh ([ctx|h]), g_Wdh
// ---------------------------------------------------------------------------
__global__ void prep_repack(const float* __restrict__ W_ih,
                            const float* __restrict__ W_hh,
                            const float* __restrict__ W_out,
                            const float* __restrict__ W_dec) {
    int stride = gridDim.x * blockDim.x;
    int g = blockIdx.x * blockDim.x + threadIdx.x;
    for (int idx = g; idx < 256 * 1536; idx += stride) {
        int i = idx / 1536, c = idx % 1536;
        int seg = c >> 8, cc = c & 255;
        float v;
        switch (seg) {
            case 0:  v = W_ih[(size_t)i * 336 + 80 + cc]; break;          // r, ctx
            case 1:  v = W_hh[(size_t)i * 256 + cc]; break;               // r, h
            case 2:  v = W_ih[(size_t)(256 + i) * 336 + 80 + cc]; break;  // z, ctx
            case 3:  v = W_hh[(size_t)(256 + i) * 256 + cc]; break;       // z, h
            case 4:  v = W_ih[(size_t)(512 + i) * 336 + 80 + cc]; break;  // n, ctx
            default: v = W_hh[(size_t)(512 + i) * 256 + cc]; break;       // n, h
        }
        g_WGh[idx] = __float2half(v);
    }
    for (int idx = g; idx < 80 * 512; idx += stride) {
        int r = idx >> 9, c = idx & 511;
        float v = (c < 256) ? W_out[(size_t)r * 512 + 256 + c]
                            : W_out[(size_t)r * 512 + (c - 256)];
        g_WOh[idx] = __float2half(v);
    }
    for (int idx = g; idx < 128 * 256; idx += stride)
        g_Wdh[idx] = __float2half(W_dec[idx]);
}

// ---------------------------------------------------------------------------
// prep_encproj: g_eph[m][a] = enc[m][:] . W_enc[a][:]
// ---------------------------------------------------------------------------
__global__ void __launch_bounds__(256) prep_encproj(const float* __restrict__ enc,
                                                    const float* __restrict__ W_enc) {
    __shared__ float x[16 * ED];
    int m0 = blockIdx.x * 16;
    int tid = threadIdx.x;
    const float4* src = (const float4*)(enc + (size_t)m0 * ED);
    float4* xd = (float4*)x;
    #pragma unroll
    for (int q = 0; q < 4; ++q) xd[tid + 256 * q] = src[tid + 256 * q];
    __syncthreads();

    int a = tid & 127, half = tid >> 7;
    const float4* wr = (const float4*)(W_enc + (size_t)a * ED);
    float acc[8] = {0.f, 0.f, 0.f, 0.f, 0.f, 0.f, 0.f, 0.f};
    for (int k4 = 0; k4 < 64; ++k4) {
        float4 wv = wr[k4];
        #pragma unroll
        for (int i = 0; i < 8; ++i) {
            float4 xv = xd[(8 * half + i) * 64 + k4];
            acc[i] += dot4(wv, xv);
        }
    }
    #pragma unroll
    for (int i = 0; i < 8; ++i)
        g_eph[(size_t)(m0 + 8 * half + i) * AD + a] = __float2half(acc[i]);
}

// ---------------------------------------------------------------------------
// prep_transpose: enc (b,t,e) fp32 -> g_encTh (b,e,t) fp16
// ---------------------------------------------------------------------------
__global__ void prep_transpose(const float* __restrict__ enc) {
    __shared__ float tile[32][33];
    int b = blockIdx.z;
    int t0 = blockIdx.x * 32, e0 = blockIdx.y * 32;
    int tx = threadIdx.x, ty = threadIdx.y;
    #pragma unroll
    for (int k = 0; k < 4; ++k)
        tile[ty + 8 * k][tx] = enc[((size_t)b * TE + t0 + ty + 8 * k) * ED + e0 + tx];
    __syncthreads();
    #pragma unroll
    for (int k = 0; k < 4; ++k)
        g_encTh[((size_t)b * ED + e0 + ty + 8 * k) * TE + t0 + tx] =
            __float2half(tile[tx][ty + 8 * k]);
}

// ---------------------------------------------------------------------------
// prep_gix: g_gix[m][r] = gt[m][:80] . W_ih[r][:80] + folded bias (fp32)
// ---------------------------------------------------------------------------
__global__ void __launch_bounds__(256) prep_gix(const float* __restrict__ gt,
                                                const float* __restrict__ W_ih,
                                                const float* __restrict__ b_ih,
                                                const float* __restrict__ b_hh) {
    __shared__ float x[8 * ID];
    int m0 = blockIdx.x * 8;
    int tid = threadIdx.x;
    if (tid < 160) ((float4*)x)[tid] = ((const float4*)(gt + (size_t)m0 * ID))[tid];
    __syncthreads();

    #pragma unroll
    for (int j = 0; j < 3; ++j) {
        int r = 256 * j + tid;
        const float* wr = W_ih + (size_t)r * 336;
        float acc[8] = {0.f, 0.f, 0.f, 0.f, 0.f, 0.f, 0.f, 0.f};
        #pragma unroll 4
        for (int k4 = 0; k4 < 20; ++k4) {
            float4 wv = *(const float4*)(wr + 4 * k4);
            #pragma unroll
            for (int i = 0; i < 8; ++i) {
                float4 xv = ((float4*)x)[i * 20 + k4];
                acc[i] += dot4(wv, xv);
            }
        }
        float bias = (r < 512) ? (b_ih[r] + b_hh[r]) : b_ih[r];
        #pragma unroll
        for (int i = 0; i < 8; ++i)
            g_gix[(size_t)(m0 + i) * 768 + r] = acc[i] + bias;
    }
}

// ---------------------------------------------------------------------------
// Decoder workspace (lives in dynamic SMEM after the weight slice)
// ---------------------------------------------------------------------------
struct Work {
    float buf[2][512];   // ping-pong [ctx(256);h(256)]
    float attn[800];     // exp(scores), unnormalized
    float dp[128];
    float o[2][80];      // double-buffered logits (deferred log_softmax)
    float pre[4][64];
    float red[32];
    float misc[4];
};
#define WG_SLICE_BYTES (64 * 1536 * 2)
#define DSMEM_BYTES (WG_SLICE_BYTES + (int)sizeof(Work))

// ---------------------------------------------------------------------------
// Decoder: 4-CTA cluster per batch, 1024 thr/CTA. GRU weights SMEM-resident.
// rank rk owns: gates [64rk,+64), dp rows [32rk,+32), scores t [200rk,+200),
// ctx e [64rk,+64), logits o [20rk,+20).
// ---------------------------------------------------------------------------
__global__ void __launch_bounds__(1024, 1) __cluster_dims__(4, 1, 1)
decoder_kernel(const float* __restrict__ b_attn,
               const float* __restrict__ v_attn,
               const float* __restrict__ b_hh,
               const float* __restrict__ b_out,
               float* __restrict__ out) {
    extern __shared__ char dsm[];
    __half* sWG = (__half*)dsm;                       // [64][1536]
    Work* Wk = (Work*)(dsm + WG_SLICE_BYTES);

    const int b = blockIdx.x >> 2;
    uint32_t rk;
    asm("mov.u32 %0, %%cluster_ctarank;" : "=r"(rk));
    const int tid = threadIdx.x, w = tid >> 5, l = tid & 31;

    // one-time: copy this CTA's GRU weight slice into SMEM.
    // Slice = 64*1536 halves = 196608 B = 12288 uint4 -> 12 iters x 1024 thr.
    {
        const uint4* src = (const uint4*)(g_WGh + (size_t)(64 * rk) * 1536);
        uint4* dst = (uint4*)sWG;
        #pragma unroll
        for (int i = 0; i < 12; ++i) dst[tid + 1024 * i] = src[tid + 1024 * i];
    }
    if (tid < 512) Wk->buf[0][tid] = 0.f;

    const float4 vf = *(const float4*)(v_attn + 4 * l);
    const __half* eph_b = g_eph + (size_t)b * TE * AD;
    const __half* eTh_b = g_encTh + (size_t)b * ED * TE;
    const size_t attn_base = (size_t)BB * TD * ID;
    __syncthreads();
    cluster_sync();

    int p = 0;
    for (int t = 0; t < TD; ++t) {
        const float* gix = g_gix + ((size_t)b * TD + t) * 768;

        // input vector [ctx;h]: lane l holds cols [8l,8l+8) of each half
        float4 ia0 = *(const float4*)(Wk->buf[p] + 8 * l);
        float4 ia1 = *(const float4*)(Wk->buf[p] + 8 * l + 4);
        float4 ib0 = *(const float4*)(Wk->buf[p] + 256 + 8 * l);
        float4 ib1 = *(const float4*)(Wk->buf[p] + 256 + 8 * l + 4);

        // ---- GRU: each warp computes r,z,n dots for 2 hidden units ------
        #pragma unroll
        for (int ii = 0; ii < 2; ++ii) {
            int il = w * 2 + ii;
            int ig = 64 * (int)rk + il;
            const uint4* wr = (const uint4*)(sWG + (size_t)il * 1536);
            float4 A, B, C, D;
            uint4 u0 = wr[l], u1 = wr[32 + l];                // r gate
            h8tof8(u0, A, B); h8tof8(u1, C, D);
            float accR = dot4(A, ia0) + dot4(B, ia1) + dot4(C, ib0) + dot4(D, ib1);
            uint4 u2 = wr[64 + l], u3 = wr[96 + l];           // z gate
            h8tof8(u2, A, B); h8tof8(u3, C, D);
            float accZ = dot4(A, ia0) + dot4(B, ia1) + dot4(C, ib0) + dot4(D, ib1);
            uint4 u4 = wr[128 + l];                           // n gate, ctx part
            h8tof8(u4, A, B);
            float accB = dot4(A, ia0) + dot4(B, ia1);
            uint4 u5 = wr[160 + l];                           // n gate, h part
            h8tof8(u5, C, D);
            float accC = dot4(C, ib0) + dot4(D, ib1);
            accR = wsum(accR); accZ = wsum(accZ);
            accB = wsum(accB); accC = wsum(accC);
            if (l == 0) {
                Wk->pre[0][il] = accR + gix[ig];
                Wk->pre[1][il] = accZ + gix[256 + ig];
                Wk->pre[2][il] = accB + gix[512 + ig];
                Wk->pre[3][il] = accC;
            }
        }
        __syncthreads();
        if (tid < 64) {
            int ig = 64 * (int)rk + tid;
            float r = 1.f / (1.f + __expf(-Wk->pre[0][tid]));
            float z = 1.f / (1.f + __expf(-Wk->pre[1][tid]));
            float hn = Wk->pre[3][tid] + b_hh[512 + ig];
            float n = tanhf(fmaf(r, hn, Wk->pre[2][tid]));
            float ho = Wk->buf[p][256 + ig];
            bcast4(&Wk->buf[p ^ 1][256 + ig], fmaf(z, ho - n, n));
        }
        cluster_sync();  // #1: h_new visible everywhere

        // ---- dec_proj: one row per warp (fp16 weights from L2) ----------
        {
            float4 h0 = *(const float4*)(Wk->buf[p ^ 1] + 256 + 4 * l);
            float4 h1 = *(const float4*)(Wk->buf[p ^ 1] + 384 + 4 * l);
            int a = 32 * (int)rk + w;
            const uint2* wr = (const uint2*)(g_Wdh + (size_t)a * 256);
            float4 d0 = h4tof4(wr[l]);
            float4 d1 = h4tof4(wr[32 + l]);
            float acc = dot4(d0, h0) + dot4(d1, h1);
            acc = wsum(acc);
            if (l == 0) bcast4(&Wk->dp[a], acc + b_attn[a]);
        }
        // ---- deferred log_softmax of previous step (rank0, warp31) ------
        if (t > 0 && rk == 0 && w == 31) {
            const float* oo = Wk->o[(t - 1) & 1];
            float v0 = oo[l];
            float v1 = oo[32 + l];
            float v2 = (l < 16) ? oo[64 + l] : -1e30f;
            float mm = wallmax(fmaxf(fmaxf(v0, v1), v2));
            float se = __expf(v0 - mm) + __expf(v1 - mm) +
                       ((l < 16) ? __expf(v2 - mm) : 0.f);
            se = wallsum(se);
            float ls = mm + logf(se);
            float* pr = out + ((size_t)b * TD + (t - 1)) * ID;
            pr[l] = v0 - ls;
            pr[32 + l] = v1 - ls;
            if (l < 16) pr[64 + l] = v2 - ls;
        }
        cluster_sync();  // #2: dp visible

        // ---- scores: exp(v . tanh(ep + dp)), fp16 ep --------------------
        {
            float4 dp = *(const float4*)(Wk->dp + 4 * l);
            for (int tt = w; tt < 200; tt += 32) {
                int tg = 200 * (int)rk + tt;
                float4 ep = h4tof4(((const uint2*)(eph_b + (size_t)tg * AD))[l]);
                float s = vf.x * ftanh(ep.x + dp.x);
                s = fmaf(vf.y, ftanh(ep.y + dp.y), s);
                s = fmaf(vf.z, ftanh(ep.z + dp.z), s);
                s = fmaf(vf.w, ftanh(ep.w + dp.w), s);
                s = wsum(s);
                if (l == 0) bcast4(&Wk->attn[tg], __expf(s));  // |s| small, safe
            }
        }
        cluster_sync();  // #3: all 800 exp-scores visible

        // ---- normalizer (redundant per CTA) + attn output ---------------
        float sv = (tid < 800) ? Wk->attn[tid] : 0.f;
        sv = wsum(sv);
        if (l == 0) Wk->red[w] = sv;
        __syncthreads();
        if (w == 0) {
            float v2 = wsum(Wk->red[l]);
            if (l == 0) Wk->misc[0] = 1.f / v2;
        }
        __syncthreads();
        float inv = Wk->misc[0];
        if (tid < 200) {
            int tg = 200 * (int)rk + tid;
            out[attn_base + ((size_t)b * TD + t) * TE + tg] = Wk->attn[tg] * inv;
        }

        // ---- ctx: 2 e per warp, fp16 encT, dot over 800 -----------------
        #pragma unroll
        for (int j = 0; j < 2; ++j) {
            int e = 64 * (int)rk + w + 32 * j;
            const uint4* er = (const uint4*)(eTh_b + (size_t)e * TE);
            float acc = 0.f;
            #pragma unroll
            for (int k = 0; k < 3; ++k) {
                float4 A, B;
                h8tof8(er[l + 32 * k], A, B);
                float4 a0 = *(const float4*)(Wk->attn + 8 * (l + 32 * k));
                float4 a1 = *(const float4*)(Wk->attn + 8 * (l + 32 * k) + 4);
                acc += dot4(A, a0) + dot4(B, a1);
            }
            if (l < 4) {
                float4 A, B;
                h8tof8(er[96 + l], A, B);
                float4 a0 = *(const float4*)(Wk->attn + 768 + 8 * l);
                float4 a1 = *(const float4*)(Wk->attn + 768 + 8 * l + 4);
                acc += dot4(A, a0) + dot4(B, a1);
            }
            acc = wsum(acc);
            if (l == 0) bcast4(&Wk->buf[p ^ 1][e], acc * inv);
        }
        cluster_sync();  // #4: ctx visible

        // ---- output logits: 20 rows per CTA -> rank 0 (deferred softmax)
        {
            float4 c0 = *(const float4*)(Wk->buf[p ^ 1] + 8 * l);
            float4 c1 = *(const float4*)(Wk->buf[p ^ 1] + 8 * l + 4);
            float4 c2 = *(const float4*)(Wk->buf[p ^ 1] + 256 + 8 * l);
            float4 c3 = *(const float4*)(Wk->buf[p ^ 1] + 256 + 8 * l + 4);
            if (w < 20) {
                int og = 20 * (int)rk + w;
                const uint4* wr = (const uint4*)(g_WOh + (size_t)og * 512);
                float4 A, B, C, D;
                h8tof8(wr[l], A, B);
                h8tof8(wr[32 + l], C, D);
                float acc = dot4(A, c0) + dot4(B, c1) + dot4(C, c2) + dot4(D, c3);
                acc = wsum(acc);
                if (l == 0) st_cluster(smem_u32(&Wk->o[t & 1][og]), 0, acc + b_out[og]);
            }
        }
        p ^= 1;
        // logits visibility for step t is provided by sync #1 of step t+1
    }

    // final flush: log_softmax for the last step
    cluster_sync();
    if (rk == 0 && w == 0) {
        const float* oo = Wk->o[(TD - 1) & 1];
        float v0 = oo[l];
        float v1 = oo[32 + l];
        float v2 = (l < 16) ? oo[64 + l] : -1e30f;
        float mm = wallmax(fmaxf(fmaxf(v0, v1), v2));
        float se = __expf(v0 - mm) + __expf(v1 - mm) +
                   ((l < 16) ? __expf(v2 - mm) : 0.f);
        se = wallsum(se);
        float ls = mm + logf(se);
        float* pr = out + ((size_t)b * TD + (TD - 1)) * ID;
        pr[l] = v0 - ls;
        pr[32 + l] = v1 - ls;
        if (l < 16) pr[64 + l] = v2 - ls;
    }
}

// ---------------------------------------------------------------------------
// Launch
// ---------------------------------------------------------------------------
extern "C" void kernel_launch(void* const* d_in, const int* in_sizes, int n_in,
                              void* d_out, int out_size) {
    const float* enc    = (const float*)d_in[0];
    const float* gt     = (const float*)d_in[1];
    const float* W_ih   = (const float*)d_in[2];
    const float* W_hh   = (const float*)d_in[3];
    const float* b_ih   = (const float*)d_in[4];
    const float* b_hh   = (const float*)d_in[5];
    const float* W_enc  = (const float*)d_in[6];
    const float* W_dec  = (const float*)d_in[7];
    const float* b_attn = (const float*)d_in[8];
    const float* v_attn = (const float*)d_in[9];
    const float* W_out  = (const float*)d_in[10];
    const float* b_out  = (const float*)d_in[11];
    float* out = (float*)d_out;

    cudaFuncSetAttribute(decoder_kernel,
                         cudaFuncAttributeMaxDynamicSharedMemorySize, DSMEM_BYTES);

    prep_repack<<<256, 256>>>(W_ih, W_hh, W_out, W_dec);
    prep_encproj<<<BB * TE / 16, 256>>>(enc, W_enc);
    prep_transpose<<<dim3(TE / 32, ED / 32, BB), dim3(32, 8)>>>(enc);
    prep_gix<<<BB * TD / 8, 256>>>(gt, W_ih, b_ih, b_hh);
    decoder_kernel<<<BB * 4, 1024, DSMEM_BYTES>>>(b_attn, v_attn, b_hh, b_out, out);
}